// round 1
// baseline (speedup 1.0000x reference)
#include <cuda_runtime.h>
#include <math_constants.h>

// ---------------------------------------------------------------------------
// GraphConvolution: out = softmax_col(P1 @ P2^T) @ (x@W) + bias
//   B=8, N=2048, F=512 (all fp32)
// Scratch lives in __device__ globals (no allocation allowed).
// ---------------------------------------------------------------------------

__device__ float g_support[8LL * 2048 * 512];   // 32 MB
__device__ float g_p1     [8LL * 2048 * 512];   // 32 MB
__device__ float g_p2     [8LL * 2048 * 512];   // 32 MB
__device__ float g_adj    [8LL * 2048 * 2048];  // 128 MB
__device__ float g_pmax   [8 * 8 * 2048];
__device__ float g_psum   [8 * 8 * 2048];
__device__ float g_cmax   [8 * 2048];
__device__ float g_rcs    [8 * 2048];

// ---- packed f32x2 helpers (Blackwell FFMA2: 2x fp32 throughput) ----
__device__ __forceinline__ unsigned long long dup2(float x) {
    unsigned long long r;
    asm("mov.b64 %0, {%1, %1};" : "=l"(r) : "f"(x));
    return r;
}
__device__ __forceinline__ void ffma2(unsigned long long& d,
                                      unsigned long long a,
                                      unsigned long long b) {
    asm("fma.rn.f32x2 %0, %1, %2, %0;" : "+l"(d) : "l"(a), "l"(b));
}
__device__ __forceinline__ float2 unpack2(unsigned long long v) {
    float2 r;
    asm("mov.b64 {%0, %1}, %2;" : "=f"(r.x), "=f"(r.y) : "l"(v));
    return r;
}

// ---------------------------------------------------------------------------
// Generic tiled GEMM: C[M,N] = A[M,K] @ op(B) (+ optional fused softmax on A,
// optional bias). BM=BN=128, BK=16, 256 threads, 8x8 per-thread tile computed
// as 8x(4 packed f32x2) accumulators.
//  TRANSB=false: B is [K,N] row-major.   TRANSB=true: B is [N,K] row-major.
//  SOFTA: A element at (row,k) is transformed exp(a - cmax[k]) * rcs[k].
// ---------------------------------------------------------------------------
template <bool TRANSB, bool SOFTA, bool BIAS>
__global__ void __launch_bounds__(256)
gemm_kernel(const float* __restrict__ A, const float* __restrict__ Bm,
            float* __restrict__ C, const float* __restrict__ bias,
            const float* __restrict__ cmax, const float* __restrict__ rcs,
            int M, int N, int K,
            long long sA, long long sB, long long sC, long long sS) {
    __shared__ float As[16][132];
    __shared__ float Bs[16][132];

    const int bz = blockIdx.z;
    const float* Ab = A + bz * sA;
    const float* Bb = Bm + bz * sB;
    float* Cb = C + bz * sC;
    const float* cm = SOFTA ? (cmax + bz * sS) : nullptr;
    const float* rc = SOFTA ? (rcs + bz * sS) : nullptr;

    const int tid  = threadIdx.x;
    const int row0 = blockIdx.y * 128;
    const int col0 = blockIdx.x * 128;
    const int rm   = (tid >> 4) << 3;   // 0..120 step 8
    const int cn   = (tid & 15) << 3;   // 0..120 step 8

    unsigned long long acc[8][4];
#pragma unroll
    for (int i = 0; i < 8; i++)
#pragma unroll
        for (int j = 0; j < 4; j++) acc[i][j] = 0ULL;

    for (int kt = 0; kt < K; kt += 16) {
        // ---- A tile: 128 rows x 16 k, float4 loads, transposed store ----
#pragma unroll
        for (int it = 0; it < 2; it++) {
            int idx = tid + it * 256;          // 0..511 float4s
            int r   = idx >> 2;
            int kq  = (idx & 3) << 2;
            float4 v = *reinterpret_cast<const float4*>(
                &Ab[(long long)(row0 + r) * K + kt + kq]);
            if (SOFTA) {
                int kg = kt + kq;
                v.x = __expf(v.x - cm[kg + 0]) * rc[kg + 0];
                v.y = __expf(v.y - cm[kg + 1]) * rc[kg + 1];
                v.z = __expf(v.z - cm[kg + 2]) * rc[kg + 2];
                v.w = __expf(v.w - cm[kg + 3]) * rc[kg + 3];
            }
            As[kq + 0][r] = v.x;
            As[kq + 1][r] = v.y;
            As[kq + 2][r] = v.z;
            As[kq + 3][r] = v.w;
        }
        // ---- B tile ----
        if (!TRANSB) {
#pragma unroll
            for (int it = 0; it < 2; it++) {
                int idx = tid + it * 256;
                int k   = idx >> 5;
                int n4  = (idx & 31) << 2;
                *reinterpret_cast<float4*>(&Bs[k][n4]) =
                    *reinterpret_cast<const float4*>(
                        &Bb[(long long)(kt + k) * N + col0 + n4]);
            }
        } else {
#pragma unroll
            for (int it = 0; it < 2; it++) {
                int idx = tid + it * 256;
                int n   = idx >> 2;
                int kq  = (idx & 3) << 2;
                float4 v = *reinterpret_cast<const float4*>(
                    &Bb[(long long)(col0 + n) * K + kt + kq]);
                Bs[kq + 0][n] = v.x;
                Bs[kq + 1][n] = v.y;
                Bs[kq + 2][n] = v.z;
                Bs[kq + 3][n] = v.w;
            }
        }
        __syncthreads();

        // ---- compute: 16 k-steps x 32 FFMA2 ----
#pragma unroll
        for (int k = 0; k < 16; k++) {
            float4 a0 = *reinterpret_cast<const float4*>(&As[k][rm]);
            float4 a1 = *reinterpret_cast<const float4*>(&As[k][rm + 4]);
            unsigned long long bp[4];
#pragma unroll
            for (int j = 0; j < 4; j++)
                bp[j] = *reinterpret_cast<const unsigned long long*>(
                    &Bs[k][cn + j * 2]);
            unsigned long long ap[8];
            ap[0] = dup2(a0.x); ap[1] = dup2(a0.y);
            ap[2] = dup2(a0.z); ap[3] = dup2(a0.w);
            ap[4] = dup2(a1.x); ap[5] = dup2(a1.y);
            ap[6] = dup2(a1.z); ap[7] = dup2(a1.w);
#pragma unroll
            for (int i = 0; i < 8; i++)
#pragma unroll
                for (int j = 0; j < 4; j++) ffma2(acc[i][j], ap[i], bp[j]);
        }
        __syncthreads();
    }

    // ---- epilogue ----
#pragma unroll
    for (int i = 0; i < 8; i++) {
        long long row = row0 + rm + i;
        float o[8];
#pragma unroll
        for (int j = 0; j < 4; j++) {
            float2 v = unpack2(acc[i][j]);
            o[j * 2]     = v.x;
            o[j * 2 + 1] = v.y;
        }
        if (BIAS) {
#pragma unroll
            for (int j = 0; j < 8; j++) o[j] += bias[col0 + cn + j];
        }
        *reinterpret_cast<float4*>(&Cb[row * N + col0 + cn]) =
            make_float4(o[0], o[1], o[2], o[3]);
        *reinterpret_cast<float4*>(&Cb[row * N + col0 + cn + 4]) =
            make_float4(o[4], o[5], o[6], o[7]);
    }
}

// ---------------------------------------------------------------------------
// Column softmax stats over adj[b, n, m], softmax axis = n.
// Stage 1: per (b, n-chunk of 256 rows) online (max, sum) per column.
// ---------------------------------------------------------------------------
__global__ void col_softmax_part() {
    const int b  = blockIdx.z;
    const int nc = blockIdx.y;
    const int mc = blockIdx.x;
    const int m  = mc * 256 + threadIdx.x;
    const float* base = g_adj + ((long long)(b * 2048 + nc * 256)) * 2048 + m;

    float mx = -CUDART_INF_F;
    float s  = 0.0f;
#pragma unroll 4
    for (int n = 0; n < 256; n++) {
        float v  = base[(long long)n * 2048];
        float nm = fmaxf(mx, v);
        s  = s * __expf(mx - nm) + __expf(v - nm);
        mx = nm;
    }
    g_pmax[(b * 8 + nc) * 2048 + m] = mx;
    g_psum[(b * 8 + nc) * 2048 + m] = s;
}

__global__ void col_softmax_combine() {
    const int idx = blockIdx.x * 256 + threadIdx.x;   // b*2048 + m
    const int b = idx >> 11;
    const int m = idx & 2047;
    float mx = -CUDART_INF_F;
    float s  = 0.0f;
#pragma unroll
    for (int nc = 0; nc < 8; nc++) {
        float pm = g_pmax[(b * 8 + nc) * 2048 + m];
        float ps = g_psum[(b * 8 + nc) * 2048 + m];
        float nm = fmaxf(mx, pm);
        s  = s * __expf(mx - nm) + ps * __expf(pm - nm);
        mx = nm;
    }
    g_cmax[idx] = mx;
    g_rcs[idx]  = 1.0f / s;
}

// ---------------------------------------------------------------------------
extern "C" void kernel_launch(void* const* d_in, const int* in_sizes, int n_in,
                              void* d_out, int out_size) {
    const float* x      = (const float*)d_in[0];
    const float* weight = (const float*)d_in[1];
    const float* bias   = (const float*)d_in[2];
    const float* w_one  = (const float*)d_in[3];
    const float* w_two  = (const float*)d_in[4];
    float* out = (float*)d_out;

    float *sup, *p1, *p2, *adj, *cm, *rc;
    cudaGetSymbolAddress((void**)&sup, g_support);
    cudaGetSymbolAddress((void**)&p1,  g_p1);
    cudaGetSymbolAddress((void**)&p2,  g_p2);
    cudaGetSymbolAddress((void**)&adj, g_adj);
    cudaGetSymbolAddress((void**)&cm,  g_cmax);
    cudaGetSymbolAddress((void**)&rc,  g_rcs);

    const long long NF  = 2048LL * 512;
    const long long NN2 = 2048LL * 2048;
    dim3 blk(256);

    // support[b] = x[b] @ weight                         [2048,512]
    gemm_kernel<false, false, false><<<dim3(4, 16, 8), blk>>>(
        x, weight, sup, nullptr, nullptr, nullptr,
        2048, 512, 512, NF, 0, NF, 0);
    // p1[b] = x[b] @ w_one^T                             [2048,512]
    gemm_kernel<true, false, false><<<dim3(4, 16, 8), blk>>>(
        x, w_one, p1, nullptr, nullptr, nullptr,
        2048, 512, 512, NF, 0, NF, 0);
    // p2[b] = x[b] @ w_two^T                             [2048,512]
    gemm_kernel<true, false, false><<<dim3(4, 16, 8), blk>>>(
        x, w_two, p2, nullptr, nullptr, nullptr,
        2048, 512, 512, NF, 0, NF, 0);
    // adj[b] = p1[b] @ p2[b]^T                           [2048,2048]
    gemm_kernel<true, false, false><<<dim3(16, 16, 8), blk>>>(
        p1, p2, adj, nullptr, nullptr, nullptr,
        2048, 2048, 512, NF, NF, NN2, 0);
    // column softmax stats (softmax over n, per column m)
    col_softmax_part<<<dim3(8, 8, 8), blk>>>();
    col_softmax_combine<<<64, blk>>>();
    // out[b] = softmax(adj[b]) @ support[b] + bias       [2048,512]
    gemm_kernel<false, true, true><<<dim3(4, 16, 8), blk>>>(
        adj, sup, out, bias, cm, rc,
        2048, 512, 2048, NN2, NF, NF, 2048);
}

// round 4
// speedup vs baseline: 2.0439x; 2.0439x over previous
#include <cuda_runtime.h>
#include <cuda_bf16.h>
#include <math_constants.h>
#include <cstdint>

// ===========================================================================
// GraphConvolution via mma.sync bf16x3 (Ootomo split) GEMMs (sm_103 base ISA).
//   supportT = wT @ x^T ; p1 = x @ w1^T ; p2 = x @ w2^T
//   adj = p1 @ p2^T ; P = softmax_col(adj) ; out = P @ supportT^T + bias
// All GEMMs: D[M,N] = A[M,K] @ B[N,K]^T, K-major bf16 hi/lo operands.
// ===========================================================================

#define NF  (2048LL * 512)
#define NN2 (2048LL * 2048)

__device__ float g_adj[8LL * 2048 * 2048];                       // 128 MB
__device__ __align__(16) __nv_bfloat16 g_xh[8LL*2048*512], g_xl[8LL*2048*512];
__device__ __align__(16) __nv_bfloat16 g_wTh[512*512],  g_wTl[512*512];
__device__ __align__(16) __nv_bfloat16 g_w1h[512*512],  g_w1l[512*512];
__device__ __align__(16) __nv_bfloat16 g_w2h[512*512],  g_w2l[512*512];
__device__ __align__(16) __nv_bfloat16 g_p1h[8LL*2048*512], g_p1l[8LL*2048*512];
__device__ __align__(16) __nv_bfloat16 g_p2h[8LL*2048*512], g_p2l[8LL*2048*512];
__device__ __align__(16) __nv_bfloat16 g_sTh[8LL*512*2048], g_sTl[8LL*512*2048];
__device__ float g_pmax[8*8*2048], g_psum[8*8*2048];
__device__ float g_cmax[8*2048],   g_rcs[8*2048];

// ---------------------------------------------------------------------------
__device__ __forceinline__ uint32_t smem_u32(const void* p) {
    uint32_t a;
    asm("{ .reg .u64 t; cvta.to.shared.u64 t, %1; cvt.u32.u64 %0, t; }"
        : "=r"(a) : "l"(p));
    return a;
}
__device__ __forceinline__ void cpa16(uint32_t s, const void* g) {
    asm volatile("cp.async.cg.shared.global [%0], [%1], 16;" :: "r"(s), "l"(g));
}
#define CP_COMMIT() asm volatile("cp.async.commit_group;" ::: "memory")
#define CP_WAIT(n)  asm volatile("cp.async.wait_group %0;" :: "n"(n) : "memory")

__device__ __forceinline__ void ldsm4(uint32_t* r, uint32_t addr) {
    asm volatile("ldmatrix.sync.aligned.m8n8.x4.shared.b16 {%0,%1,%2,%3}, [%4];"
        : "=r"(r[0]), "=r"(r[1]), "=r"(r[2]), "=r"(r[3]) : "r"(addr));
}
__device__ __forceinline__ void mma_bf16(float* d, const uint32_t* a,
                                         const uint32_t* b) {
    asm volatile(
        "mma.sync.aligned.m16n8k16.row.col.f32.bf16.bf16.f32 "
        "{%0,%1,%2,%3}, {%4,%5,%6,%7}, {%8,%9}, {%0,%1,%2,%3};"
        : "+f"(d[0]), "+f"(d[1]), "+f"(d[2]), "+f"(d[3])
        : "r"(a[0]), "r"(a[1]), "r"(a[2]), "r"(a[3]), "r"(b[0]), "r"(b[1]));
}

struct alignas(16) BF8 { __nv_bfloat16 v[8]; };
struct alignas(8)  BF4 { __nv_bfloat16 v[4]; };

__device__ __forceinline__ void split2(float x, __nv_bfloat16& h, __nv_bfloat16& l) {
    h = __float2bfloat16(x);
    l = __float2bfloat16(x - __bfloat162float(h));
}

// smem tile layout: [128 rows][4 kchunks of 16B], XOR-swizzled for ldmatrix.
__device__ __forceinline__ uint32_t swz(int r, int c) {
    return (uint32_t)(r * 64 + ((c ^ ((r >> 1) & 3)) << 4));
}

// ---------------------------------------------------------------------------
// bf16x3 GEMM. BM=BN=128, BK=32, 256 threads, 8 warps (4m x 2n), warp 32x64.
// EPI: 0 fp32, 1 bf16 hi/lo split, 2 fp32+bias.
// SOFTA: A is fp32 adj; a(row,k) = exp(adj - cmax[k]) * rcs[k], split on the fly.
// ---------------------------------------------------------------------------
static constexpr int S_ALO = 8192, S_BHI = 16384;
static constexpr int S_STAGE = 32768;
static constexpr int SM_TOTAL = 2 * S_STAGE;   // 64 KB dynamic

template <int EPI, bool SOFTA>
__global__ void __launch_bounds__(256, 1)
gemm_mma(const __nv_bfloat16* __restrict__ Ah, const __nv_bfloat16* __restrict__ Al,
         const float* __restrict__ Af,
         const __nv_bfloat16* __restrict__ Bh, const __nv_bfloat16* __restrict__ Bl,
         float* __restrict__ C, __nv_bfloat16* __restrict__ Chi,
         __nv_bfloat16* __restrict__ Clo,
         const float* __restrict__ bias, const float* __restrict__ cmax,
         const float* __restrict__ rcs,
         int M, int N, int K,
         long long sA, long long sB, long long sC, long long sS) {
    extern __shared__ char smem[];
    const uint32_t sb = smem_u32(smem);
    const int tid = threadIdx.x;
    const int wid = tid >> 5, lane = tid & 31;
    const int wm = wid & 3, wn = wid >> 2;
    const int row0 = blockIdx.y * 128, col0 = blockIdx.x * 128;
    const int bz = blockIdx.z;

    if (!SOFTA) { Ah += bz * sA; Al += bz * sA; }
    else        { Af += bz * sA; cmax += bz * sS; rcs += bz * sS; }
    Bh += bz * sB; Bl += bz * sB;

    float d[2][8][4];
#pragma unroll
    for (int i = 0; i < 2; i++)
#pragma unroll
        for (int j = 0; j < 8; j++)
#pragma unroll
            for (int q = 0; q < 4; q++) d[i][j][q] = 0.0f;

    const int r_ld = tid >> 2;           // 0..63 base row for loads
    const int c_ld = tid & 3;            // kchunk

    // ---- stage loader ----
    auto load_stage = [&](int buf, int kt) {
        const uint32_t st = sb + buf * S_STAGE;
#pragma unroll
        for (int p = 0; p < 2; p++) {
            int r = r_ld + p * 64;
            size_t go = (size_t)(row0 + r) * K + kt + c_ld * 8;
            uint32_t sa = st + swz(r, c_ld);
            if (!SOFTA) {
                cpa16(sa, Ah + go);
                cpa16(sa + S_ALO, Al + go);
            } else {
                const float* ap = Af + go;
                float4 v0 = *reinterpret_cast<const float4*>(ap);
                float4 v1 = *reinterpret_cast<const float4*>(ap + 4);
                int kg = kt + c_ld * 8;
                float4 m0 = *reinterpret_cast<const float4*>(cmax + kg);
                float4 m1 = *reinterpret_cast<const float4*>(cmax + kg + 4);
                float4 s0 = *reinterpret_cast<const float4*>(rcs + kg);
                float4 s1 = *reinterpret_cast<const float4*>(rcs + kg + 4);
                float pv[8] = { __expf(v0.x-m0.x)*s0.x, __expf(v0.y-m0.y)*s0.y,
                                __expf(v0.z-m0.z)*s0.z, __expf(v0.w-m0.w)*s0.w,
                                __expf(v1.x-m1.x)*s1.x, __expf(v1.y-m1.y)*s1.y,
                                __expf(v1.z-m1.z)*s1.z, __expf(v1.w-m1.w)*s1.w };
                BF8 hh, ll;
#pragma unroll
                for (int t = 0; t < 8; t++) split2(pv[t], hh.v[t], ll.v[t]);
                *reinterpret_cast<BF8*>(smem + (sa - sb))          = hh;
                *reinterpret_cast<BF8*>(smem + (sa + S_ALO - sb))  = ll;
            }
        }
#pragma unroll
        for (int p = 0; p < 2; p++) {
            int r = r_ld + p * 64;
            size_t go = (size_t)(col0 + r) * K + kt + c_ld * 8;
            uint32_t sa = st + S_BHI + swz(r, c_ld);
            cpa16(sa, Bh + go);
            cpa16(sa + 8192, Bl + go);
        }
        CP_COMMIT();
    };

    const int KT = K >> 5;
    load_stage(0, 0);

    for (int it = 0; it < KT; it++) {
        const bool pre = (it + 1 < KT);
        if (pre) load_stage((it + 1) & 1, (it + 1) << 5);
        if (pre) CP_WAIT(1); else CP_WAIT(0);
        __syncthreads();

        const uint32_t st = sb + (it & 1) * S_STAGE;
#pragma unroll
        for (int k16 = 0; k16 < 2; k16++) {
            uint32_t ah[2][4], al[2][4];
#pragma unroll
            for (int mi = 0; mi < 2; mi++) {
                int arow = wm * 32 + mi * 16 + (lane & 15);
                int akc  = k16 * 2 + (lane >> 4);
                uint32_t ad = st + swz(arow, akc);
                ldsm4(ah[mi], ad);
                ldsm4(al[mi], ad + S_ALO);
            }
            uint32_t bh[8][2], bl[8][2];
#pragma unroll
            for (int bj = 0; bj < 4; bj++) {
                int g = lane >> 3;
                int nrow = wn * 64 + bj * 16 + (g >> 1) * 8 + (lane & 7);
                int kc = k16 * 2 + (g & 1);
                uint32_t bd = st + S_BHI + swz(nrow, kc);
                uint32_t t[4];
                ldsm4(t, bd);
                bh[bj*2][0] = t[0]; bh[bj*2][1] = t[1];
                bh[bj*2+1][0] = t[2]; bh[bj*2+1][1] = t[3];
                ldsm4(t, bd + 8192);
                bl[bj*2][0] = t[0]; bl[bj*2][1] = t[1];
                bl[bj*2+1][0] = t[2]; bl[bj*2+1][1] = t[3];
            }
#pragma unroll
            for (int mi = 0; mi < 2; mi++)
#pragma unroll
                for (int nj = 0; nj < 8; nj++)
                    mma_bf16(d[mi][nj], ah[mi], bh[nj]);
#pragma unroll
            for (int mi = 0; mi < 2; mi++)
#pragma unroll
                for (int nj = 0; nj < 8; nj++)
                    mma_bf16(d[mi][nj], ah[mi], bl[nj]);
#pragma unroll
            for (int mi = 0; mi < 2; mi++)
#pragma unroll
                for (int nj = 0; nj < 8; nj++)
                    mma_bf16(d[mi][nj], al[mi], bh[nj]);
        }
        __syncthreads();
    }

    // ---- epilogue (register -> global, float2 granules) ----
    C   += bz * sC;
    Chi += bz * sC;
    Clo += bz * sC;
#pragma unroll
    for (int mi = 0; mi < 2; mi++) {
#pragma unroll
        for (int nj = 0; nj < 8; nj++) {
            int r = row0 + wm * 32 + mi * 16 + (lane >> 2);
            int c = col0 + wn * 64 + nj * 8 + (lane & 3) * 2;
#pragma unroll
            for (int hh = 0; hh < 2; hh++) {
                size_t go = (size_t)(r + hh * 8) * N + c;
                float vx = d[mi][nj][hh * 2], vy = d[mi][nj][hh * 2 + 1];
                if (EPI == 0) {
                    *reinterpret_cast<float2*>(&C[go]) = make_float2(vx, vy);
                } else if (EPI == 2) {
                    *reinterpret_cast<float2*>(&C[go]) =
                        make_float2(vx + bias[c], vy + bias[c + 1]);
                } else {
                    __nv_bfloat16 h0, l0, h1, l1;
                    split2(vx, h0, l0);
                    split2(vy, h1, l1);
                    *reinterpret_cast<__nv_bfloat162*>(&Chi[go]) =
                        __nv_bfloat162(h0, h1);
                    *reinterpret_cast<__nv_bfloat162*>(&Clo[go]) =
                        __nv_bfloat162(l0, l1);
                }
            }
        }
    }
}

// ---------------------------------------------------------------------------
// Conversions
// ---------------------------------------------------------------------------
__global__ void split_f32(const float* __restrict__ src, __nv_bfloat16* __restrict__ hi,
                          __nv_bfloat16* __restrict__ lo) {
    size_t i = ((size_t)blockIdx.x * 256 + threadIdx.x) * 4;
    float4 v = *reinterpret_cast<const float4*>(src + i);
    BF4 h, l;
    split2(v.x, h.v[0], l.v[0]); split2(v.y, h.v[1], l.v[1]);
    split2(v.z, h.v[2], l.v[2]); split2(v.w, h.v[3], l.v[3]);
    *reinterpret_cast<BF4*>(hi + i) = h;
    *reinterpret_cast<BF4*>(lo + i) = l;
}

__global__ void transpose_split(const float* __restrict__ w,
                                __nv_bfloat16* __restrict__ th,
                                __nv_bfloat16* __restrict__ tl) {
    __shared__ float t[32][33];
    int fx = blockIdx.x * 32, fy = blockIdx.y * 32;
    int tx = threadIdx.x, ty = threadIdx.y;
#pragma unroll
    for (int j = 0; j < 4; j++)
        t[ty + 8 * j][tx] = w[(size_t)(fy + ty + 8 * j) * 512 + fx + tx];
    __syncthreads();
#pragma unroll
    for (int j = 0; j < 4; j++) {
        float v = t[tx][ty + 8 * j];
        __nv_bfloat16 h, l;
        split2(v, h, l);
        size_t o = (size_t)(fx + ty + 8 * j) * 512 + fy + tx;
        th[o] = h; tl[o] = l;
    }
}

// ---------------------------------------------------------------------------
// Column softmax stats (softmax over n for each column m)
// ---------------------------------------------------------------------------
__global__ void col_softmax_part() {
    const int b = blockIdx.z, nc = blockIdx.y, mc = blockIdx.x;
    const int m = mc * 256 + threadIdx.x;
    const float* base = g_adj + ((long long)(b * 2048 + nc * 256)) * 2048 + m;
    float mx = -CUDART_INF_F, s = 0.0f;
#pragma unroll 4
    for (int n = 0; n < 256; n++) {
        float v = base[(long long)n * 2048];
        float nm = fmaxf(mx, v);
        s = s * __expf(mx - nm) + __expf(v - nm);
        mx = nm;
    }
    g_pmax[(b * 8 + nc) * 2048 + m] = mx;
    g_psum[(b * 8 + nc) * 2048 + m] = s;
}

__global__ void col_softmax_combine() {
    const int idx = blockIdx.x * 256 + threadIdx.x;
    const int b = idx >> 11, m = idx & 2047;
    float mx = -CUDART_INF_F, s = 0.0f;
#pragma unroll
    for (int nc = 0; nc < 8; nc++) {
        float pm = g_pmax[(b * 8 + nc) * 2048 + m];
        float ps = g_psum[(b * 8 + nc) * 2048 + m];
        float nm = fmaxf(mx, pm);
        s = s * __expf(mx - nm) + ps * __expf(pm - nm);
        mx = nm;
    }
    g_cmax[idx] = mx;
    g_rcs[idx]  = 1.0f / s;
}

// ---------------------------------------------------------------------------
extern "C" void kernel_launch(void* const* d_in, const int* in_sizes, int n_in,
                              void* d_out, int out_size) {
    const float* x      = (const float*)d_in[0];
    const float* weight = (const float*)d_in[1];
    const float* bias   = (const float*)d_in[2];
    const float* w_one  = (const float*)d_in[3];
    const float* w_two  = (const float*)d_in[4];
    float* out = (float*)d_out;

    float *adj, *cm, *rc;
    __nv_bfloat16 *xh, *xl, *wTh, *wTl, *w1h, *w1l, *w2h, *w2l;
    __nv_bfloat16 *p1h, *p1l, *p2h, *p2l, *sTh, *sTl;
    cudaGetSymbolAddress((void**)&adj, g_adj);
    cudaGetSymbolAddress((void**)&cm,  g_cmax);
    cudaGetSymbolAddress((void**)&rc,  g_rcs);
    cudaGetSymbolAddress((void**)&xh,  g_xh);  cudaGetSymbolAddress((void**)&xl,  g_xl);
    cudaGetSymbolAddress((void**)&wTh, g_wTh); cudaGetSymbolAddress((void**)&wTl, g_wTl);
    cudaGetSymbolAddress((void**)&w1h, g_w1h); cudaGetSymbolAddress((void**)&w1l, g_w1l);
    cudaGetSymbolAddress((void**)&w2h, g_w2h); cudaGetSymbolAddress((void**)&w2l, g_w2l);
    cudaGetSymbolAddress((void**)&p1h, g_p1h); cudaGetSymbolAddress((void**)&p1l, g_p1l);
    cudaGetSymbolAddress((void**)&p2h, g_p2h); cudaGetSymbolAddress((void**)&p2l, g_p2l);
    cudaGetSymbolAddress((void**)&sTh, g_sTh); cudaGetSymbolAddress((void**)&sTl, g_sTl);

    cudaFuncSetAttribute(gemm_mma<0,false>, cudaFuncAttributeMaxDynamicSharedMemorySize, SM_TOTAL);
    cudaFuncSetAttribute(gemm_mma<1,false>, cudaFuncAttributeMaxDynamicSharedMemorySize, SM_TOTAL);
    cudaFuncSetAttribute(gemm_mma<2,true>,  cudaFuncAttributeMaxDynamicSharedMemorySize, SM_TOTAL);

    dim3 blk(256);

    // conversions
    split_f32<<<8192, blk>>>(x, xh, xl);
    transpose_split<<<dim3(16,16), dim3(32,8)>>>(weight, wTh, wTl);
    split_f32<<<256, blk>>>(w_one, w1h, w1l);
    split_f32<<<256, blk>>>(w_two, w2h, w2l);

    // supportT[b] = wT @ x[b]^T            [512, 2048] bf16 split out
    gemm_mma<1,false><<<dim3(16,4,8), blk, SM_TOTAL>>>(
        wTh, wTl, nullptr, xh, xl, nullptr, sTh, sTl, nullptr, nullptr, nullptr,
        512, 2048, 512, 0, NF, NF, 0);
    // p1[b] = x[b] @ w1^T                  [2048, 512] bf16 split out
    gemm_mma<1,false><<<dim3(4,16,8), blk, SM_TOTAL>>>(
        xh, xl, nullptr, w1h, w1l, nullptr, p1h, p1l, nullptr, nullptr, nullptr,
        2048, 512, 512, NF, 0, NF, 0);
    // p2[b] = x[b] @ w2^T
    gemm_mma<1,false><<<dim3(4,16,8), blk, SM_TOTAL>>>(
        xh, xl, nullptr, w2h, w2l, nullptr, p2h, p2l, nullptr, nullptr, nullptr,
        2048, 512, 512, NF, 0, NF, 0);
    // adj[b] = p1[b] @ p2[b]^T             [2048, 2048] fp32
    gemm_mma<0,false><<<dim3(16,16,8), blk, SM_TOTAL>>>(
        p1h, p1l, nullptr, p2h, p2l, adj, nullptr, nullptr, nullptr, nullptr, nullptr,
        2048, 2048, 512, NF, NF, NN2, 0);
    // softmax stats
    col_softmax_part<<<dim3(8,8,8), blk>>>();
    col_softmax_combine<<<64, blk>>>();
    // out[b] = softmax(adj[b]) @ supportT[b]^T + bias     [2048, 512] fp32
    gemm_mma<2,true><<<dim3(4,16,8), blk, SM_TOTAL>>>(
        nullptr, nullptr, adj, sTh, sTl, out, nullptr, nullptr, bias, cm, rc,
        2048, 512, 2048, NN2, NF, NF, 2048);
}